// round 15
// baseline (speedup 1.0000x reference)
#include <cuda_runtime.h>
#include <cuda.h>
#include <cuda_fp16.h>
#include <cstdint>

// ---------------- constants ----------------
#define NUMF    41024
#define KH      36480               // HMMA k-range (570 chunks x 64); FFMA covers the rest
#define KFX     4544                // FFMA k-columns = NUMF - KH = 568 * 8
#define CHPM    570                 // chunks per M-tile
#define NMT     64                  // M-tiles (32 white + 32 black)
#define TOTC    (NMT * CHPM)        // 36480 total chunk-columns
#define GRID1   148                 // one CTA per SM
#define STAGES  3
#define ASTG    32768               // A: 2 sub-tiles x (128 rows x 128B) fp32
#define BSTG    32768               // B: 256 rows x 128B fp16 (64 k)
#define XSTG    4096                // A-extra: 128 rows x 32B fp32 (8 k)
#define STGB    (ASTG + BSTG + XSTG)   // 69632
#define SMEM1   (2048 + STAGES * STGB) // 210944

// per-CTA partials: [cta][part 0/1][128 rows x 256 neurons]
__device__ float g_part[GRID1][2][128 * 256];
// dense accumulator (+b0): rows 0..4095 white, 4096..8191 black
__device__ float g_acc[8192 * 256];
// W0 pre-converted to fp16, fragment-packed per 64-half group
__device__ __align__(1024) __half g_w0h[256 * NUMF];

// ---------------- device helpers ----------------
__device__ __forceinline__ uint32_t smem_u32(const void* p) {
    uint32_t a;
    asm("{ .reg .u64 t; cvta.to.shared.u64 t, %1; cvt.u32.u64 %0, t; }" : "=r"(a) : "l"(p));
    return a;
}
__device__ __forceinline__ void mbar_init(uint32_t a, uint32_t c) {
    asm volatile("mbarrier.init.shared.b64 [%0], %1;" :: "r"(a), "r"(c) : "memory");
}
__device__ __forceinline__ void mbar_expect_tx(uint32_t a, uint32_t b) {
    asm volatile("mbarrier.arrive.expect_tx.shared.b64 _, [%0], %1;" :: "r"(a), "r"(b) : "memory");
}
__device__ __forceinline__ void mbar_arrive(uint32_t a) {
    asm volatile("mbarrier.arrive.shared.b64 _, [%0];" :: "r"(a) : "memory");
}
__device__ __forceinline__ void mbar_wait(uint32_t mbar, uint32_t parity) {
    asm volatile(
        "{\n\t.reg .pred P;\n\t"
        "LW_%=:\n\t"
        "mbarrier.try_wait.parity.acquire.cta.shared::cta.b64 P, [%0], %1, 0x989680;\n\t"
        "@P bra.uni LD_%=;\n\t"
        "bra.uni LW_%=;\n\t"
        "LD_%=:\n\t}"
        :: "r"(mbar), "r"(parity) : "memory");
}
__device__ __forceinline__ void tma2d(uint32_t dst, const CUtensorMap* m, int x, int y, uint32_t mbar) {
    asm volatile(
        "cp.async.bulk.tensor.2d.shared::cta.global.tile.mbarrier::complete_tx::bytes "
        "[%0], [%1, {%2, %3}], [%4];"
        :: "r"(dst), "l"(m), "r"(x), "r"(y), "r"(mbar) : "memory");
}
// pack two fp32 -> f16x2 {lo, hi}
__device__ __forceinline__ uint32_t f2h2(float lo, float hi) {
    uint32_t r;
    asm("cvt.rn.f16x2.f32 %0, %2, %1;" : "=r"(r) : "f"(lo), "f"(hi));
    return r;
}
__device__ __forceinline__ void mma_f16(float* c, const uint32_t* a, const uint32_t* b) {
    asm volatile(
        "mma.sync.aligned.m16n8k16.row.col.f32.f16.f16.f32 "
        "{%0,%1,%2,%3}, {%4,%5,%6,%7}, {%8,%9}, {%0,%1,%2,%3};"
        : "+f"(c[0]), "+f"(c[1]), "+f"(c[2]), "+f"(c[3])
        : "r"(a[0]), "r"(a[1]), "r"(a[2]), "r"(a[3]), "r"(b[0]), "r"(b[1]));
}

// ---------------- kernel 0: convert W0 -> fragment-packed fp16 (vectorized) ----------------
__global__ void __launch_bounds__(512) nn_cvt(const float* __restrict__ W0) {
    const int n = blockIdx.x;                 // 0..255
    const float* src = W0 + (size_t)n * NUMF;
    __half* dst = g_w0h + (size_t)n * NUMF;
    for (int d4 = threadIdx.x; d4 < NUMF / 4; d4 += 512) {
        int d = d4 << 2;
        int r = d & 63, base = d & ~63;
        int slot = r >> 2;
        int t  = (slot & 1) | ((slot >> 3) << 1);
        int st = (slot >> 1) & 1;
        int c  = (slot >> 2) & 1;
        int K0 = base + c * 32 + 16 * (t >> 1) + 2 * (t & 1) + 8 * st;
        float2 v0 = *(const float2*)(src + K0);
        float2 v1 = *(const float2*)(src + K0 + 4);
        uint2 o;
        o.x = f2h2(v0.x, v0.y);
        o.y = f2h2(v1.x, v1.y);
        *(uint2*)(dst + d) = o;
    }
}

// ---------------- kernel 1: layer-0 GEMM (fp16 HMMA + fp32 FFMA co-compute) ----------------
__global__ void __launch_bounds__(288, 1) nn_gemm(
    const __grid_constant__ CUtensorMap tmW,
    const __grid_constant__ CUtensorMap tmB,
    const __grid_constant__ CUtensorMap tmW0h,
    const __grid_constant__ CUtensorMap tmWx,
    const __grid_constant__ CUtensorMap tmBx,
    const float* __restrict__ W0g)
{
    extern __shared__ char raw[];
    char* base = (char*)(((uintptr_t)raw + 1023u) & ~(uintptr_t)1023u);
    uint32_t base_u   = smem_u32(base);
    uint32_t mb_full  = base_u;            // STAGES x 8B
    uint32_t mb_empty = base_u + 512;      // STAGES x 8B
    char* tiles       = base + 1024;
    uint32_t tiles_u  = base_u + 1024;

    const int tid  = threadIdx.x;
    const int wid  = tid >> 5;
    const int lane = tid & 31;
    const int bid  = blockIdx.x;

    const int cs = (int)((long long)bid * TOTC / GRID1);        // start chunk
    const int ce = (int)((long long)(bid + 1) * TOTC / GRID1);  // end chunk
    const int nc = ce - cs;                                     // 246 or 247
    const int mt0 = cs / CHPM;
    const int mt1 = (ce - 1) / CHPM;                            // mt0 or mt0+1

    if (tid == 0) {
        for (int s = 0; s < STAGES; s++) {
            mbar_init(mb_full  + s * 8, 1);
            mbar_init(mb_empty + s * 8, 256);
        }
        asm volatile("fence.proxy.async.shared::cta;" ::: "memory");
    }
    __syncthreads();

    if (wid == 8) {
        if (lane == 0) {
            // ---------------- producer ----------------
#define ISSUE(c_, s_) do {                                           \
            int mt_ = (c_) / CHPM;                                   \
            int kc_ = (c_) - mt_ * CHPM;                             \
            const CUtensorMap* mp_ = (mt_ < 32) ? &tmW : &tmB;       \
            const CUtensorMap* mx_ = (mt_ < 32) ? &tmWx : &tmBx;     \
            uint32_t mb_ = mb_full + (s_) * 8;                       \
            int ex_ = (kc_ < 568);                                   \
            mbar_expect_tx(mb_, ex_ ? STGB : (ASTG + BSTG));         \
            uint32_t t_ = tiles_u + (s_) * STGB;                     \
            int ro_ = (mt_ & 31) * 128;                              \
            tma2d(t_,         mp_,   kc_ * 64,      ro_, mb_);       \
            tma2d(t_ + 16384, mp_,   kc_ * 64 + 32, ro_, mb_);       \
            tma2d(t_ + 32768, &tmW0h, kc_ * 64,     0,   mb_);       \
            if (ex_) tma2d(t_ + 65536, mx_, KH + kc_ * 8, ro_, mb_); \
        } while (0)
            ISSUE(cs, 0); ISSUE(cs + 1, 1); ISSUE(cs + 2, 2);
            int s = 0, ep = 0;
            for (int j = STAGES; j < nc; j++) {
                mbar_wait(mb_empty + s * 8, ep);
                ISSUE(cs + j, s);
                if (++s == STAGES) { s = 0; ep ^= 1; }
            }
#undef ISSUE
        }
    } else {
        // ---------------- consumers ----------------
        const int wm = (wid >> 2) * 64;      // warp M offset (0/64)
        const int wn = (wid & 3) * 64;       // warp N offset (0/64/128/192)
        const int g  = lane >> 2;            // 0..7
        const int t  = lane & 3;             // 0..3

        // A: conflict-free swizzled byte offsets (validated R7); st = kstep&1
        int aoff[2][2];
        #pragma unroll
        for (int s_ = 0; s_ < 2; s_++)
            #pragma unroll
            for (int h_ = 0; h_ < 2; h_++)
                aoff[s_][h_] = ((32 * s_ + 16 * h_ + 8 * (t & 1) + 64 * (t >> 1)) ^ (g << 4));
        // B: one LDS.64 per (ni, kstep); slot = P(t) + 2*st + 4*c
        const int Pt = (t & 1) + 8 * (t >> 1);
        int boff[4];
        #pragma unroll
        for (int ks = 0; ks < 4; ks++)
            boff[ks] = (((Pt + 2 * (ks & 1) + 4 * (ks >> 1)) * 8) ^ (g << 4));

        float c[4][8][4];
        #pragma unroll
        for (int mi = 0; mi < 4; mi++)
            #pragma unroll
            for (int ni = 0; ni < 8; ni++)
                #pragma unroll
                for (int r = 0; r < 4; r++) c[mi][ni][r] = 0.f;

        // local index of the last chunk of part 0 (or -1 if single part)
        const int jb = (mt1 > mt0) ? ((mt0 + 1) * CHPM - 1 - cs) : -1;

        int s = 0, fp = 0;
        int kc = cs - mt0 * CHPM;            // chunk index within current M-tile
        for (int j = 0; j < nc; j++) {
            mbar_wait(mb_full + s * 8, fp);
            const char* Ast = tiles + s * STGB;
            const char* Bst = Ast + ASTG;
            const char* Axt = Ast + (ASTG + BSTG);
            const bool ex = (kc < 568);
            const long long kfx = KH + kc * 8;

            #pragma unroll
            for (int ks = 0; ks < 4; ks++) {
                const char* Asub = Ast + (ks >> 1) * 16384;
                const int st = ks & 1;
                uint32_t a[4][4];
                #pragma unroll
                for (int mi = 0; mi < 4; mi++) {
                    const char* pr = Asub + (wm + mi * 16 + g) * 128;
                    float2 v00 = *(const float2*)(pr + aoff[st][0]);
                    float2 v10 = *(const float2*)(pr + 1024 + aoff[st][0]);
                    float2 v01 = *(const float2*)(pr + aoff[st][1]);
                    float2 v11 = *(const float2*)(pr + 1024 + aoff[st][1]);
                    a[mi][0] = f2h2(v00.x, v00.y);
                    a[mi][1] = f2h2(v10.x, v10.y);
                    a[mi][2] = f2h2(v01.x, v01.y);
                    a[mi][3] = f2h2(v11.x, v11.y);
                }
                uint32_t b[8][2];
                #pragma unroll
                for (int ni = 0; ni < 8; ni++) {
                    uint2 v = *(const uint2*)(Bst + (wn + ni * 8 + g) * 128 + boff[ks]);
                    b[ni][0] = v.x; b[ni][1] = v.y;
                }
                #pragma unroll
                for (int mi = 0; mi < 4; mi++)
                    #pragma unroll
                    for (int ni = 0; ni < 8; ni++)
                        mma_f16(c[mi][ni], a[mi], b[ni]);

                // ---- FFMA co-compute: 2 extra k-columns per HMMA k-step ----
                if (ex) {
                    const int q = ks;            // quarter = kx pair {2q, 2q+1}
                    float av[8][2];
                    #pragma unroll
                    for (int r8 = 0; r8 < 8; r8++) {
                        int row = wm + (r8 >> 1) * 16 + (r8 & 1) * 8 + g;
                        float2 v = *(const float2*)(Axt + row * 32 + q * 8);
                        av[r8][0] = v.x; av[r8][1] = v.y;
                    }
                    #pragma unroll
                    for (int ni = 0; ni < 8; ni++) {
                        const float* wp = W0g + (size_t)(wn + ni * 8 + (t << 1)) * NUMF + kfx + q * 2;
                        float2 b0 = *(const float2*)(wp);
                        float2 b1 = *(const float2*)(wp + NUMF);
                        #pragma unroll
                        for (int mi = 0; mi < 4; mi++) {
                            c[mi][ni][0] += av[2*mi][0]   * b0.x;
                            c[mi][ni][1] += av[2*mi][0]   * b1.x;
                            c[mi][ni][2] += av[2*mi+1][0] * b0.x;
                            c[mi][ni][3] += av[2*mi+1][0] * b1.x;
                            c[mi][ni][0] += av[2*mi][1]   * b0.y;
                            c[mi][ni][1] += av[2*mi][1]   * b1.y;
                            c[mi][ni][2] += av[2*mi+1][1] * b0.y;
                            c[mi][ni][3] += av[2*mi+1][1] * b1.y;
                        }
                    }
                }
            }
            mbar_arrive(mb_empty + s * 8);
            if (++s == STAGES) { s = 0; fp ^= 1; }

            if (j == jb) {
                // flush part 0, reset accumulators
                float* dst = g_part[bid][0];
                #pragma unroll
                for (int ni = 0; ni < 8; ni++) {
                    const int col = wn + ni * 8 + (t << 1);
                    #pragma unroll
                    for (int mi = 0; mi < 4; mi++) {
                        const int r = wm + mi * 16 + g;
                        *(float2*)(dst + (size_t)r * 256 + col)       = make_float2(c[mi][ni][0], c[mi][ni][1]);
                        *(float2*)(dst + (size_t)(r + 8) * 256 + col) = make_float2(c[mi][ni][2], c[mi][ni][3]);
                        c[mi][ni][0] = c[mi][ni][1] = c[mi][ni][2] = c[mi][ni][3] = 0.f;
                    }
                }
                kc = 0;
            } else {
                kc++;
            }
        }

        // final flush (part 1 if two parts, else part 0)
        {
            float* dst = g_part[bid][(mt1 > mt0) ? 1 : 0];
            #pragma unroll
            for (int ni = 0; ni < 8; ni++) {
                const int col = wn + ni * 8 + (t << 1);
                #pragma unroll
                for (int mi = 0; mi < 4; mi++) {
                    const int r = wm + mi * 16 + g;
                    *(float2*)(dst + (size_t)r * 256 + col)       = make_float2(c[mi][ni][0], c[mi][ni][1]);
                    *(float2*)(dst + (size_t)(r + 8) * 256 + col) = make_float2(c[mi][ni][2], c[mi][ni][3]);
                }
            }
        }
    }
}

// ---------------- kernel 1.5: reduce partials -> dense g_acc (+b0) ----------------
__device__ __forceinline__ int cover_cta(int c) {
    return (int)(((long long)(c + 1) * GRID1 - 1) / TOTC);
}
__device__ __forceinline__ int gather_parts(int mt, const float** ptr) {
    int c0 = mt * CHPM;
    int iA = cover_cta(c0);
    int iB = cover_cta(c0 + CHPM - 1);
    int n = 0;
    for (int i = iA; i <= iB && n < 4; i++) {
        int si = (int)((long long)i * TOTC / GRID1);
        int slot = (si / CHPM == mt) ? 0 : 1;
        ptr[n++] = g_part[i][slot];
    }
    return n;
}

__global__ void __launch_bounds__(256) nn_reduce(const float* __restrict__ b0) {
    const int mt   = blockIdx.x >> 3;       // M-tile 0..63
    const int slab = blockIdx.x & 7;        // rows [slab*16, slab*16+16)
    const float* ps[4];
    const int n = gather_parts(mt, ps);

    const int base = slab * 16 * 256;       // float offset within tile
    float* dst = g_acc + (size_t)mt * 128 * 256 + base;
    const float4* b0v = (const float4*)b0;

    for (int i = threadIdx.x; i < 1024; i += 256) {
        float4 s = b0v[i & 63];
        #pragma unroll 4
        for (int k = 0; k < 4; k++) {
            if (k < n) {
                float4 v = ((const float4*)(ps[k] + base))[i];
                s.x += v.x; s.y += v.y; s.z += v.z; s.w += v.w;
            }
        }
        ((float4*)dst)[i] = s;
    }
}

// ---------------- kernel 2: blend + clip + small MLP head (vectorized, 4-acc) ----------------
#define SW1_PITCH 516
#define SW2_PITCH 36
#define SMEM2 ((32*SW1_PITCH + 32*SW2_PITCH + 16*512 + 16*32) * 4)

__device__ __forceinline__ float4 clip4(float4 v) {
    v.x = fminf(fmaxf(v.x, 0.f), 1.f);
    v.y = fminf(fmaxf(v.y, 0.f), 1.f);
    v.z = fminf(fmaxf(v.z, 0.f), 1.f);
    v.w = fminf(fmaxf(v.w, 0.f), 1.f);
    return v;
}

__global__ void __launch_bounds__(512) nn_head(
    const float* __restrict__ stm,
    const float* __restrict__ W1, const float* __restrict__ b1,
    const float* __restrict__ W2, const float* __restrict__ b2,
    const float* __restrict__ W3, const float* __restrict__ b3,
    float* __restrict__ out)
{
    extern __shared__ float sm[];
    float* sW1 = sm;                               // 32 x 516
    float* sW2 = sW1 + 32 * SW1_PITCH;             // 32 x 36
    float* sl1 = sW2 + 32 * SW2_PITCH;             // 16 warps x 512
    float* sl2 = sl1 + 16 * 512;                   // 16 warps x 32

    int tid = threadIdx.x;
    int w = tid >> 5, j = tid & 31;
    int b = blockIdx.x * 16 + w;

    const float4* aw = (const float4*)(g_acc + (size_t)b * 256);
    const float4* ab = (const float4*)(g_acc + (size_t)(4096 + b) * 256);
    float4 wv0 = aw[j],      bv0 = ab[j];
    float4 wv1 = aw[32 + j], bv1 = ab[32 + j];
    float s = stm[b];

    for (int i = tid; i < 32 * 512; i += 512) sW1[(i >> 9) * SW1_PITCH + (i & 511)] = W1[i];
    for (int i = tid; i < 32 * 32;  i += 512) sW2[(i >> 5) * SW2_PITCH + (i & 31)]  = W2[i];
    __syncthreads();

    float4* l14 = (float4*)(sl1 + w * 512);
    float*  l2  = sl2 + w * 32;
    float bj1 = b1[j], bj2 = b2[j], w3j = W3[j], b3v = b3[0];
    const float t1 = 1.f - s;

    {
        float4 x0, x1, y0, y1;
        x0.x = s*wv0.x + t1*bv0.x; x0.y = s*wv0.y + t1*bv0.y; x0.z = s*wv0.z + t1*bv0.z; x0.w = s*wv0.w + t1*bv0.w;
        y0.x = s*bv0.x + t1*wv0.x; y0.y = s*bv0.y + t1*wv0.y; y0.z = s*bv0.z + t1*wv0.z; y0.w = s*bv0.w + t1*wv0.w;
        x1.x = s*wv1.x + t1*bv1.x; x1.y = s*wv1.y + t1*bv1.y; x1.z = s*wv1.z + t1*bv1.z; x1.w = s*wv1.w + t1*bv1.w;
        y1.x = s*bv1.x + t1*wv1.x; y1.y = s*bv1.y + t1*wv1.y; y1.z = s*bv1.z + t1*wv1.z; y1.w = s*bv1.w + t1*wv1.w;
        l14[j]       = clip4(x0);
        l14[32 + j]  = clip4(x1);
        l14[64 + j]  = clip4(y0);
        l14[96 + j]  = clip4(y1);
    }
    __syncwarp();

    float a0 = bj1, a1 = 0.f, a2c = 0.f, a3c = 0.f;
    const float4* wr = (const float4*)(sW1 + j * SW1_PITCH);
    #pragma unroll 16
    for (int k = 0; k < 128; k++) {
        float4 v = wr[k], u = l14[k];
        a0  += v.x * u.x;
        a1  += v.y * u.y;
        a2c += v.z * u.z;
        a3c += v.w * u.w;
    }
    float a2 = fminf(fmaxf((a0 + a1) + (a2c + a3c), 0.f), 1.f);
    l2[j] = a2;
    __syncwarp();

    float c0 = bj2, c1 = 0.f, c2 = 0.f, c3 = 0.f;
    const float4* wr2 = (const float4*)(sW2 + j * SW2_PITCH);
    const float4* l24 = (const float4*)l2;
    #pragma unroll
    for (int k = 0; k < 8; k++) {
        float4 v = wr2[k], u = l24[k];
        c0 += v.x * u.x; c1 += v.y * u.y; c2 += v.z * u.z; c3 += v.w * u.w;
    }
    float a3 = fminf(fmaxf((c0 + c1) + (c2 + c3), 0.f), 1.f);
    float v = w3j * a3;
    #pragma unroll
    for (int o = 16; o > 0; o >>= 1) v += __shfl_xor_sync(0xffffffffu, v, o);
    if (j == 0) out[b] = v + b3v;
}

// ---------------- host ----------------
typedef CUresult (*EncodeFn)(CUtensorMap*, CUtensorMapDataType, cuuint32_t, void*,
                             const cuuint64_t*, const cuuint64_t*, const cuuint32_t*, const cuuint32_t*,
                             CUtensorMapInterleave, CUtensorMapSwizzle,
                             CUtensorMapL2promotion, CUtensorMapFloatOOBfill);

static EncodeFn get_encoder() {
    void* p = nullptr;
    cudaDriverEntryPointQueryResult qr;
    cudaGetDriverEntryPointByVersion("cuTensorMapEncodeTiled", &p, 12000, cudaEnableDefault, &qr);
    return (EncodeFn)p;
}

static void encode_f32(CUtensorMap* m, const void* ptr, unsigned long long rows) {
    cuuint64_t dims[2]    = { (cuuint64_t)NUMF, (cuuint64_t)rows };
    cuuint64_t strides[1] = { (cuuint64_t)NUMF * 4ull };
    cuuint32_t box[2]     = { 32u, 128u };      // 128B x 128 rows, SW128
    cuuint32_t es[2]      = { 1u, 1u };
    get_encoder()(m, CU_TENSOR_MAP_DATA_TYPE_FLOAT32, 2, (void*)ptr, dims, strides, box, es,
       CU_TENSOR_MAP_INTERLEAVE_NONE, CU_TENSOR_MAP_SWIZZLE_128B,
       CU_TENSOR_MAP_L2_PROMOTION_L2_128B, CU_TENSOR_MAP_FLOAT_OOB_FILL_NONE);
}

static void encode_f32x8(CUtensorMap* m, const void* ptr, unsigned long long rows) {
    cuuint64_t dims[2]    = { (cuuint64_t)NUMF, (cuuint64_t)rows };
    cuuint64_t strides[1] = { (cuuint64_t)NUMF * 4ull };
    cuuint32_t box[2]     = { 8u, 128u };       // 32B x 128 rows, no swizzle
    cuuint32_t es[2]      = { 1u, 1u };
    get_encoder()(m, CU_TENSOR_MAP_DATA_TYPE_FLOAT32, 2, (void*)ptr, dims, strides, box, es,
       CU_TENSOR_MAP_INTERLEAVE_NONE, CU_TENSOR_MAP_SWIZZLE_NONE,
       CU_TENSOR_MAP_L2_PROMOTION_L2_128B, CU_TENSOR_MAP_FLOAT_OOB_FILL_NONE);
}

static void encode_f16(CUtensorMap* m, const void* ptr, unsigned long long rows) {
    cuuint64_t dims[2]    = { (cuuint64_t)NUMF, (cuuint64_t)rows };
    cuuint64_t strides[1] = { (cuuint64_t)NUMF * 2ull };
    cuuint32_t box[2]     = { 64u, 256u };      // 128B x 256 rows, SW128
    cuuint32_t es[2]      = { 1u, 1u };
    get_encoder()(m, CU_TENSOR_MAP_DATA_TYPE_FLOAT16, 2, (void*)ptr, dims, strides, box, es,
       CU_TENSOR_MAP_INTERLEAVE_NONE, CU_TENSOR_MAP_SWIZZLE_128B,
       CU_TENSOR_MAP_L2_PROMOTION_L2_128B, CU_TENSOR_MAP_FLOAT_OOB_FILL_NONE);
}

extern "C" void kernel_launch(void* const* d_in, const int* in_sizes, int n_in,
                              void* d_out, int out_size) {
    const float* wf  = (const float*)d_in[0];
    const float* bf  = (const float*)d_in[1];
    const float* stm = (const float*)d_in[2];
    const float* W0  = (const float*)d_in[3];
    const float* b0  = (const float*)d_in[4];
    const float* W1  = (const float*)d_in[5];
    const float* b1  = (const float*)d_in[6];
    const float* W2  = (const float*)d_in[7];
    const float* b2  = (const float*)d_in[8];
    const float* W3  = (const float*)d_in[9];
    const float* b3  = (const float*)d_in[10];
    float* out = (float*)d_out;

    void* w0h_ptr = nullptr;
    cudaGetSymbolAddress(&w0h_ptr, g_w0h);

    CUtensorMap mW, mB, mW0h, mWx, mBx;
    encode_f32(&mW,  wf, 4096);
    encode_f32(&mB,  bf, 4096);
    encode_f16(&mW0h, w0h_ptr, 256);
    encode_f32x8(&mWx, wf, 4096);
    encode_f32x8(&mBx, bf, 4096);

    cudaFuncSetAttribute(nn_gemm, cudaFuncAttributeMaxDynamicSharedMemorySize, SMEM1);
    cudaFuncSetAttribute(nn_head, cudaFuncAttributeMaxDynamicSharedMemorySize, SMEM2);

    nn_cvt<<<256, 512>>>(W0);
    nn_gemm<<<GRID1, 288, SMEM1>>>(mW, mB, mW0h, mWx, mBx, W0);
    nn_reduce<<<512, 256>>>(b0);
    nn_head<<<256, 512, SMEM2>>>(stm, W1, b1, W2, b2, W3, b3, out);
}

// round 16
// speedup vs baseline: 2.1016x; 2.1016x over previous
#include <cuda_runtime.h>
#include <cuda.h>
#include <cuda_fp16.h>
#include <cstdint>

// ---------------- constants ----------------
#define NUMF    41024
#define KCHUNK  64                  // k-values per pipeline chunk (= 4 k16 mma steps)
#define CHPM    641                 // chunks per M-tile (41024/64)
#define NMT     64                  // M-tiles (32 white + 32 black)
#define TOTC    (NMT * CHPM)        // 41024 total chunk-columns
#define GRID1   148                 // one CTA per SM
#define STAGES  3
#define ASTG    32768               // A: 2 sub-tiles x (128 rows x 128B) fp32
#define BSTG    32768               // B: 256 rows x 128B fp16 (64 k)
#define STGB    (ASTG + BSTG)       // 65536
#define SMEM1   (2048 + STAGES * STGB)   // 198656

// per-CTA partials: [cta][part 0/1][128 rows x 256 neurons]
__device__ float g_part[GRID1][2][128 * 256];
// W0 pre-converted to fp16, fragment-packed per 64-half group
__device__ __align__(1024) __half g_w0h[256 * NUMF];

// ---------------- device helpers ----------------
__device__ __forceinline__ uint32_t smem_u32(const void* p) {
    uint32_t a;
    asm("{ .reg .u64 t; cvta.to.shared.u64 t, %1; cvt.u32.u64 %0, t; }" : "=r"(a) : "l"(p));
    return a;
}
__device__ __forceinline__ void mbar_init(uint32_t a, uint32_t c) {
    asm volatile("mbarrier.init.shared.b64 [%0], %1;" :: "r"(a), "r"(c) : "memory");
}
__device__ __forceinline__ void mbar_expect_tx(uint32_t a, uint32_t b) {
    asm volatile("mbarrier.arrive.expect_tx.shared.b64 _, [%0], %1;" :: "r"(a), "r"(b) : "memory");
}
__device__ __forceinline__ void mbar_arrive(uint32_t a) {
    asm volatile("mbarrier.arrive.shared.b64 _, [%0];" :: "r"(a) : "memory");
}
__device__ __forceinline__ void mbar_wait(uint32_t mbar, uint32_t parity) {
    asm volatile(
        "{\n\t.reg .pred P;\n\t"
        "LW_%=:\n\t"
        "mbarrier.try_wait.parity.acquire.cta.shared::cta.b64 P, [%0], %1, 0x989680;\n\t"
        "@P bra.uni LD_%=;\n\t"
        "bra.uni LW_%=;\n\t"
        "LD_%=:\n\t}"
        :: "r"(mbar), "r"(parity) : "memory");
}
__device__ __forceinline__ void tma2d(uint32_t dst, const CUtensorMap* m, int x, int y, uint32_t mbar) {
    asm volatile(
        "cp.async.bulk.tensor.2d.shared::cta.global.tile.mbarrier::complete_tx::bytes "
        "[%0], [%1, {%2, %3}], [%4];"
        :: "r"(dst), "l"(m), "r"(x), "r"(y), "r"(mbar) : "memory");
}
// pack two fp32 -> f16x2 {lo, hi}
__device__ __forceinline__ uint32_t f2h2(float lo, float hi) {
    uint32_t r;
    asm("cvt.rn.f16x2.f32 %0, %2, %1;" : "=r"(r) : "f"(lo), "f"(hi));
    return r;
}
__device__ __forceinline__ void mma_f16(float* c, const uint32_t* a, const uint32_t* b) {
    asm volatile(
        "mma.sync.aligned.m16n8k16.row.col.f32.f16.f16.f32 "
        "{%0,%1,%2,%3}, {%4,%5,%6,%7}, {%8,%9}, {%0,%1,%2,%3};"
        : "+f"(c[0]), "+f"(c[1]), "+f"(c[2]), "+f"(c[3])
        : "r"(a[0]), "r"(a[1]), "r"(a[2]), "r"(a[3]), "r"(b[0]), "r"(b[1]));
}

// ---------------- kernel 0: convert W0 -> fragment-packed fp16 (vectorized) ----------------
__global__ void __launch_bounds__(512) nn_cvt(const float* __restrict__ W0) {
    const int n = blockIdx.x;                 // 0..255
    const float* src = W0 + (size_t)n * NUMF;
    __half* dst = g_w0h + (size_t)n * NUMF;
    for (int d4 = threadIdx.x; d4 < NUMF / 4; d4 += 512) {
        int d = d4 << 2;
        int r = d & 63, base = d & ~63;
        int slot = r >> 2;
        int t  = (slot & 1) | ((slot >> 3) << 1);
        int st = (slot >> 1) & 1;
        int c  = (slot >> 2) & 1;
        int K0 = base + c * 32 + 16 * (t >> 1) + 2 * (t & 1) + 8 * st;
        float2 v0 = *(const float2*)(src + K0);
        float2 v1 = *(const float2*)(src + K0 + 4);
        uint2 o;
        o.x = f2h2(v0.x, v0.y);
        o.y = f2h2(v1.x, v1.y);
        *(uint2*)(dst + d) = o;
    }
}

// ---------------- kernel 1: layer-0 GEMM (fp16 mma.sync, fp16 B, 148-CTA split) ----------------
__global__ void __launch_bounds__(288, 1) nn_gemm(
    const __grid_constant__ CUtensorMap tmW,
    const __grid_constant__ CUtensorMap tmB,
    const __grid_constant__ CUtensorMap tmW0h)
{
    extern __shared__ char raw[];
    char* base = (char*)(((uintptr_t)raw + 1023u) & ~(uintptr_t)1023u);
    uint32_t base_u   = smem_u32(base);
    uint32_t mb_full  = base_u;            // STAGES x 8B
    uint32_t mb_empty = base_u + 512;      // STAGES x 8B
    char* tiles       = base + 1024;
    uint32_t tiles_u  = base_u + 1024;

    const int tid  = threadIdx.x;
    const int wid  = tid >> 5;
    const int lane = tid & 31;
    const int bid  = blockIdx.x;

    const int cs = (int)((long long)bid * TOTC / GRID1);        // start chunk
    const int ce = (int)((long long)(bid + 1) * TOTC / GRID1);  // end chunk
    const int nc = ce - cs;                                     // 277 or 278
    const int mt0 = cs / CHPM;
    const int mt1 = (ce - 1) / CHPM;                            // mt0 or mt0+1

    if (tid == 0) {
        for (int s = 0; s < STAGES; s++) {
            mbar_init(mb_full  + s * 8, 1);
            mbar_init(mb_empty + s * 8, 256);
        }
        asm volatile("fence.proxy.async.shared::cta;" ::: "memory");
    }
    __syncthreads();

    if (wid == 8) {
        if (lane == 0) {
            // ---------------- producer ----------------
#define ISSUE(c_, s_) do {                                           \
            int mt_ = (c_) / CHPM;                                   \
            int kc_ = (c_) - mt_ * CHPM;                             \
            const CUtensorMap* mp_ = (mt_ < 32) ? &tmW : &tmB;       \
            uint32_t mb_ = mb_full + (s_) * 8;                       \
            mbar_expect_tx(mb_, STGB);                               \
            uint32_t t_ = tiles_u + (s_) * STGB;                     \
            tma2d(t_,         mp_,   kc_ * 64,      (mt_ & 31) * 128, mb_); \
            tma2d(t_ + 16384, mp_,   kc_ * 64 + 32, (mt_ & 31) * 128, mb_); \
            tma2d(t_ + ASTG, &tmW0h, kc_ * 64,      0,                mb_); \
        } while (0)
            ISSUE(cs, 0); ISSUE(cs + 1, 1); ISSUE(cs + 2, 2);
            int s = 0, ep = 0;
            for (int j = STAGES; j < nc; j++) {
                mbar_wait(mb_empty + s * 8, ep);
                ISSUE(cs + j, s);
                if (++s == STAGES) { s = 0; ep ^= 1; }
            }
#undef ISSUE
        }
    } else {
        // ---------------- consumers ----------------
        const int wm = (wid >> 2) * 64;      // warp M offset (0/64)
        const int wn = (wid & 3) * 64;       // warp N offset (0/64/128/192)
        const int g  = lane >> 2;            // 0..7
        const int t  = lane & 3;             // 0..3

        // A: conflict-free swizzled byte offsets (validated R7); st = kstep&1
        int aoff[2][2];
        #pragma unroll
        for (int s_ = 0; s_ < 2; s_++)
            #pragma unroll
            for (int h_ = 0; h_ < 2; h_++)
                aoff[s_][h_] = ((32 * s_ + 16 * h_ + 8 * (t & 1) + 64 * (t >> 1)) ^ (g << 4));
        // B: one LDS.64 per (ni, kstep); slot = P(t) + 2*st + 4*c
        const int Pt = (t & 1) + 8 * (t >> 1);
        int boff[4];
        #pragma unroll
        for (int ks = 0; ks < 4; ks++)
            boff[ks] = (((Pt + 2 * (ks & 1) + 4 * (ks >> 1)) * 8) ^ (g << 4));

        float c[4][8][4];
        #pragma unroll
        for (int mi = 0; mi < 4; mi++)
            #pragma unroll
            for (int ni = 0; ni < 8; ni++)
                #pragma unroll
                for (int r = 0; r < 4; r++) c[mi][ni][r] = 0.f;

        // local index of the last chunk of part 0 (or -1 if single part)
        const int jb = (mt1 > mt0) ? ((mt0 + 1) * CHPM - 1 - cs) : -1;

        int s = 0, fp = 0;
        for (int j = 0; j < nc; j++) {
            mbar_wait(mb_full + s * 8, fp);
            const char* Ast = tiles + s * STGB;
            const char* Bst = Ast + ASTG;

            #pragma unroll
            for (int ks = 0; ks < 4; ks++) {
                const char* Asub = Ast + (ks >> 1) * 16384;
                const int st = ks & 1;
                uint32_t a[4][4];
                #pragma unroll
                for (int mi = 0; mi < 4; mi++) {
                    const char* pr = Asub + (wm + mi * 16 + g) * 128;
                    float2 v00 = *(const float2*)(pr + aoff[st][0]);
                    float2 v10 = *(const float2*)(pr + 1024 + aoff[st][0]);
                    float2 v01 = *(const float2*)(pr + aoff[st][1]);
                    float2 v11 = *(const float2*)(pr + 1024 + aoff[st][1]);
                    a[mi][0] = f2h2(v00.x, v00.y);
                    a[mi][1] = f2h2(v10.x, v10.y);
                    a[mi][2] = f2h2(v01.x, v01.y);
                    a[mi][3] = f2h2(v11.x, v11.y);
                }
                uint32_t b[8][2];
                #pragma unroll
                for (int ni = 0; ni < 8; ni++) {
                    uint2 v = *(const uint2*)(Bst + (wn + ni * 8 + g) * 128 + boff[ks]);
                    b[ni][0] = v.x; b[ni][1] = v.y;
                }
                #pragma unroll
                for (int mi = 0; mi < 4; mi++)
                    #pragma unroll
                    for (int ni = 0; ni < 8; ni++)
                        mma_f16(c[mi][ni], a[mi], b[ni]);
            }
            mbar_arrive(mb_empty + s * 8);
            if (++s == STAGES) { s = 0; fp ^= 1; }

            if (j == jb) {
                // flush part 0, reset accumulators
                float* dst = g_part[bid][0];
                #pragma unroll
                for (int ni = 0; ni < 8; ni++) {
                    const int col = wn + ni * 8 + (t << 1);
                    #pragma unroll
                    for (int mi = 0; mi < 4; mi++) {
                        const int r = wm + mi * 16 + g;
                        *(float2*)(dst + (size_t)r * 256 + col)       = make_float2(c[mi][ni][0], c[mi][ni][1]);
                        *(float2*)(dst + (size_t)(r + 8) * 256 + col) = make_float2(c[mi][ni][2], c[mi][ni][3]);
                        c[mi][ni][0] = c[mi][ni][1] = c[mi][ni][2] = c[mi][ni][3] = 0.f;
                    }
                }
            }
        }

        // final flush (part 1 if two parts, else part 0)
        {
            float* dst = g_part[bid][(mt1 > mt0) ? 1 : 0];
            #pragma unroll
            for (int ni = 0; ni < 8; ni++) {
                const int col = wn + ni * 8 + (t << 1);
                #pragma unroll
                for (int mi = 0; mi < 4; mi++) {
                    const int r = wm + mi * 16 + g;
                    *(float2*)(dst + (size_t)r * 256 + col)       = make_float2(c[mi][ni][0], c[mi][ni][1]);
                    *(float2*)(dst + (size_t)(r + 8) * 256 + col) = make_float2(c[mi][ni][2], c[mi][ni][3]);
                }
            }
        }
    }
}

// ---------------- partial-cover helpers ----------------
__device__ __forceinline__ int cover_cta(int c) {
    return (int)(((long long)(c + 1) * GRID1 - 1) / TOTC);
}
__device__ __forceinline__ int gather_parts(int mt, const float** ptr) {
    int c0 = mt * CHPM;
    int iA = cover_cta(c0);
    int iB = cover_cta(c0 + CHPM - 1);
    int n = 0;
    for (int i = iA; i <= iB && n < 4; i++) {
        int si = (int)((long long)i * TOTC / GRID1);
        int slot = (si / CHPM == mt) ? 0 : 1;
        ptr[n++] = g_part[i][slot];
    }
    return n;
}

// ---------------- kernel 2: fused gather + blend + clip + small MLP head ----------------
#define SW1_PITCH 516
#define SW2_PITCH 36
#define SMEM2 ((32*SW1_PITCH + 32*SW2_PITCH + 16*512 + 16*32) * 4)

__device__ __forceinline__ float4 clip4(float4 v) {
    v.x = fminf(fmaxf(v.x, 0.f), 1.f);
    v.y = fminf(fmaxf(v.y, 0.f), 1.f);
    v.z = fminf(fmaxf(v.z, 0.f), 1.f);
    v.w = fminf(fmaxf(v.w, 0.f), 1.f);
    return v;
}
__device__ __forceinline__ void acc4(float4& a, float4 v) {
    a.x += v.x; a.y += v.y; a.z += v.z; a.w += v.w;
}

__global__ void __launch_bounds__(512) nn_head(
    const float* __restrict__ stm,
    const float* __restrict__ b0,
    const float* __restrict__ W1, const float* __restrict__ b1,
    const float* __restrict__ W2, const float* __restrict__ b2,
    const float* __restrict__ W3, const float* __restrict__ b3,
    float* __restrict__ out)
{
    extern __shared__ float sm[];
    float* sW1 = sm;                               // 32 x 516
    float* sW2 = sW1 + 32 * SW1_PITCH;             // 32 x 36
    float* sl1 = sW2 + 32 * SW2_PITCH;             // 16 warps x 512
    float* sl2 = sl1 + 16 * 512;                   // 16 warps x 32

    int tid = threadIdx.x;
    int w = tid >> 5, j = tid & 31;
    int b = blockIdx.x * 16 + w;

    // fused reduce: gather this row's partials (white + black) with b0
    const float4* b0v = (const float4*)b0;
    float4 wv0 = b0v[j], wv1 = b0v[32 + j];
    float4 bv0 = wv0,    bv1 = wv1;
    {
        const float* pw[4];
        const float* pb[4];
        int nw_ = gather_parts(b >> 7, pw);
        int nb_ = gather_parts(32 + (b >> 7), pb);
        const int lr4 = (b & 127) * 64;   // float4 offset of row within 128x256 tile
        #pragma unroll 4
        for (int k = 0; k < 4; k++) {
            if (k < nw_) {
                const float4* p = (const float4*)pw[k] + lr4;
                acc4(wv0, p[j]); acc4(wv1, p[32 + j]);
            }
        }
        #pragma unroll 4
        for (int k = 0; k < 4; k++) {
            if (k < nb_) {
                const float4* p = (const float4*)pb[k] + lr4;
                acc4(bv0, p[j]); acc4(bv1, p[32 + j]);
            }
        }
    }
    float s = stm[b];

    for (int i = tid; i < 32 * 512; i += 512) sW1[(i >> 9) * SW1_PITCH + (i & 511)] = W1[i];
    for (int i = tid; i < 32 * 32;  i += 512) sW2[(i >> 5) * SW2_PITCH + (i & 31)]  = W2[i];
    __syncthreads();

    float4* l14 = (float4*)(sl1 + w * 512);
    float*  l2  = sl2 + w * 32;
    float bj1 = b1[j], bj2 = b2[j], w3j = W3[j], b3v = b3[0];
    const float t1 = 1.f - s;

    {
        float4 x0, x1, y0, y1;
        x0.x = s*wv0.x + t1*bv0.x; x0.y = s*wv0.y + t1*bv0.y; x0.z = s*wv0.z + t1*bv0.z; x0.w = s*wv0.w + t1*bv0.w;
        y0.x = s*bv0.x + t1*wv0.x; y0.y = s*bv0.y + t1*wv0.y; y0.z = s*bv0.z + t1*wv0.z; y0.w = s*bv0.w + t1*wv0.w;
        x1.x = s*wv1.x + t1*bv1.x; x1.y = s*wv1.y + t1*bv1.y; x1.z = s*wv1.z + t1*bv1.z; x1.w = s*wv1.w + t1*bv1.w;
        y1.x = s*bv1.x + t1*wv1.x; y1.y = s*bv1.y + t1*wv1.y; y1.z = s*bv1.z + t1*wv1.z; y1.w = s*bv1.w + t1*wv1.w;
        l14[j]       = clip4(x0);
        l14[32 + j]  = clip4(x1);
        l14[64 + j]  = clip4(y0);
        l14[96 + j]  = clip4(y1);
    }
    __syncwarp();

    // L1: 512-dot with 4 independent accumulator chains, float4 LDS
    float a0 = bj1, a1 = 0.f, a2c = 0.f, a3c = 0.f;
    const float4* wr = (const float4*)(sW1 + j * SW1_PITCH);
    #pragma unroll 16
    for (int k = 0; k < 128; k++) {
        float4 v = wr[k], u = l14[k];
        a0  += v.x * u.x;
        a1  += v.y * u.y;
        a2c += v.z * u.z;
        a3c += v.w * u.w;
    }
    float a2 = fminf(fmaxf((a0 + a1) + (a2c + a3c), 0.f), 1.f);
    l2[j] = a2;
    __syncwarp();

    // L2: 32-dot, float4
    float c0 = bj2, c1 = 0.f, c2 = 0.f, c3 = 0.f;
    const float4* wr2 = (const float4*)(sW2 + j * SW2_PITCH);
    const float4* l24 = (const float4*)l2;
    #pragma unroll
    for (int k = 0; k < 8; k++) {
        float4 v = wr2[k], u = l24[k];
        c0 += v.x * u.x; c1 += v.y * u.y; c2 += v.z * u.z; c3 += v.w * u.w;
    }
    float a3 = fminf(fmaxf((c0 + c1) + (c2 + c3), 0.f), 1.f);
    float v = w3j * a3;
    #pragma unroll
    for (int o = 16; o > 0; o >>= 1) v += __shfl_xor_sync(0xffffffffu, v, o);
    if (j == 0) out[b] = v + b3v;
}

// ---------------- host ----------------
typedef CUresult (*EncodeFn)(CUtensorMap*, CUtensorMapDataType, cuuint32_t, void*,
                             const cuuint64_t*, const cuuint64_t*, const cuuint32_t*, const cuuint32_t*,
                             CUtensorMapInterleave, CUtensorMapSwizzle,
                             CUtensorMapL2promotion, CUtensorMapFloatOOBfill);

static EncodeFn get_encoder() {
    void* p = nullptr;
    cudaDriverEntryPointQueryResult qr;
    cudaGetDriverEntryPointByVersion("cuTensorMapEncodeTiled", &p, 12000, cudaEnableDefault, &qr);
    return (EncodeFn)p;
}

static void encode_f32(CUtensorMap* m, const void* ptr, unsigned long long rows) {
    cuuint64_t dims[2]    = { (cuuint64_t)NUMF, (cuuint64_t)rows };
    cuuint64_t strides[1] = { (cuuint64_t)NUMF * 4ull };
    cuuint32_t box[2]     = { 32u, 128u };      // 128B x 128 rows, SW128
    cuuint32_t es[2]      = { 1u, 1u };
    get_encoder()(m, CU_TENSOR_MAP_DATA_TYPE_FLOAT32, 2, (void*)ptr, dims, strides, box, es,
       CU_TENSOR_MAP_INTERLEAVE_NONE, CU_TENSOR_MAP_SWIZZLE_128B,
       CU_TENSOR_MAP_L2_PROMOTION_L2_128B, CU_TENSOR_MAP_FLOAT_OOB_FILL_NONE);
}

static void encode_f16(CUtensorMap* m, const void* ptr, unsigned long long rows) {
    cuuint64_t dims[2]    = { (cuuint64_t)NUMF, (cuuint64_t)rows };
    cuuint64_t strides[1] = { (cuuint64_t)NUMF * 2ull };
    cuuint32_t box[2]     = { 64u, 256u };      // 128B x 256 rows, SW128
    cuuint32_t es[2]      = { 1u, 1u };
    get_encoder()(m, CU_TENSOR_MAP_DATA_TYPE_FLOAT16, 2, (void*)ptr, dims, strides, box, es,
       CU_TENSOR_MAP_INTERLEAVE_NONE, CU_TENSOR_MAP_SWIZZLE_128B,
       CU_TENSOR_MAP_L2_PROMOTION_L2_128B, CU_TENSOR_MAP_FLOAT_OOB_FILL_NONE);
}

extern "C" void kernel_launch(void* const* d_in, const int* in_sizes, int n_in,
                              void* d_out, int out_size) {
    const float* wf  = (const float*)d_in[0];
    const float* bf  = (const float*)d_in[1];
    const float* stm = (const float*)d_in[2];
    const float* W0  = (const float*)d_in[3];
    const float* b0  = (const float*)d_in[4];
    const float* W1  = (const float*)d_in[5];
    const float* b1  = (const float*)d_in[6];
    const float* W2  = (const float*)d_in[7];
    const float* b2  = (const float*)d_in[8];
    const float* W3  = (const float*)d_in[9];
    const float* b3  = (const float*)d_in[10];
    float* out = (float*)d_out;

    void* w0h_ptr = nullptr;
    cudaGetSymbolAddress(&w0h_ptr, g_w0h);

    CUtensorMap mW, mB, mW0h;
    encode_f32(&mW,  wf, 4096);
    encode_f32(&mB,  bf, 4096);
    encode_f16(&mW0h, w0h_ptr, 256);

    cudaFuncSetAttribute(nn_gemm, cudaFuncAttributeMaxDynamicSharedMemorySize, SMEM1);
    cudaFuncSetAttribute(nn_head, cudaFuncAttributeMaxDynamicSharedMemorySize, SMEM2);

    nn_cvt<<<256, 512>>>(W0);
    nn_gemm<<<GRID1, 288, SMEM1>>>(mW, mB, mW0h);
    nn_head<<<256, 512, SMEM2>>>(stm, b0, W1, b1, W2, b2, W3, b3, out);
}

// round 17
// speedup vs baseline: 3.2100x; 1.5273x over previous
#include <cuda_runtime.h>
#include <cuda.h>
#include <cuda_fp16.h>
#include <cstdint>

// ---------------- constants ----------------
#define NUMF    41024
#define KCHUNK  64                  // k-values per pipeline chunk (= 4 k16 mma steps)
#define CHPM    641                 // chunks per M-tile (41024/64)
#define NMT     64                  // M-tiles (32 white + 32 black)
#define TOTC    (NMT * CHPM)        // 41024 total chunk-columns
#define GRID1   148                 // one CTA per SM
#define STAGES  3
#define ASTG    32768               // A: 2 sub-tiles x (128 rows x 128B) fp32
#define BSTG    32768               // B: 256 rows x 128B fp16 (64 k)
#define STGB    (ASTG + BSTG)       // 65536
#define SMEM1   (2048 + STAGES * STGB)   // 198656

// per-CTA partials: [cta][part 0/1][128 rows x 256 neurons]
__device__ float g_part[GRID1][2][128 * 256];
// dense accumulator (+b0): rows 0..4095 white, 4096..8191 black
__device__ float g_acc[8192 * 256];
// W0 pre-converted to fp16, fragment-packed per 64-half group
__device__ __align__(1024) __half g_w0h[256 * NUMF];

// ---------------- device helpers ----------------
__device__ __forceinline__ uint32_t smem_u32(const void* p) {
    uint32_t a;
    asm("{ .reg .u64 t; cvta.to.shared.u64 t, %1; cvt.u32.u64 %0, t; }" : "=r"(a) : "l"(p));
    return a;
}
__device__ __forceinline__ void mbar_init(uint32_t a, uint32_t c) {
    asm volatile("mbarrier.init.shared.b64 [%0], %1;" :: "r"(a), "r"(c) : "memory");
}
__device__ __forceinline__ void mbar_expect_tx(uint32_t a, uint32_t b) {
    asm volatile("mbarrier.arrive.expect_tx.shared.b64 _, [%0], %1;" :: "r"(a), "r"(b) : "memory");
}
__device__ __forceinline__ void mbar_arrive(uint32_t a) {
    asm volatile("mbarrier.arrive.shared.b64 _, [%0];" :: "r"(a) : "memory");
}
__device__ __forceinline__ void mbar_wait(uint32_t mbar, uint32_t parity) {
    asm volatile(
        "{\n\t.reg .pred P;\n\t"
        "LW_%=:\n\t"
        "mbarrier.try_wait.parity.acquire.cta.shared::cta.b64 P, [%0], %1, 0x989680;\n\t"
        "@P bra.uni LD_%=;\n\t"
        "bra.uni LW_%=;\n\t"
        "LD_%=:\n\t}"
        :: "r"(mbar), "r"(parity) : "memory");
}
__device__ __forceinline__ void tma2d(uint32_t dst, const CUtensorMap* m, int x, int y, uint32_t mbar) {
    asm volatile(
        "cp.async.bulk.tensor.2d.shared::cta.global.tile.mbarrier::complete_tx::bytes "
        "[%0], [%1, {%2, %3}], [%4];"
        :: "r"(dst), "l"(m), "r"(x), "r"(y), "r"(mbar) : "memory");
}
// pack two fp32 -> f16x2 {lo, hi}
__device__ __forceinline__ uint32_t f2h2(float lo, float hi) {
    uint32_t r;
    asm("cvt.rn.f16x2.f32 %0, %2, %1;" : "=r"(r) : "f"(lo), "f"(hi));
    return r;
}
__device__ __forceinline__ void mma_f16(float* c, const uint32_t* a, const uint32_t* b) {
    asm volatile(
        "mma.sync.aligned.m16n8k16.row.col.f32.f16.f16.f32 "
        "{%0,%1,%2,%3}, {%4,%5,%6,%7}, {%8,%9}, {%0,%1,%2,%3};"
        : "+f"(c[0]), "+f"(c[1]), "+f"(c[2]), "+f"(c[3])
        : "r"(a[0]), "r"(a[1]), "r"(a[2]), "r"(a[3]), "r"(b[0]), "r"(b[1]));
}

// ---------------- kernel 0: convert W0 -> fragment-packed fp16 ----------------
// 2048 CTAs: blockIdx.y = W0 row (0..255), blockIdx.x = column eighth (0..7).
// Each CTA covers 1282 4-half groups with 256 threads (<=6 iters, high MLP).
__global__ void __launch_bounds__(256) nn_cvt(const float* __restrict__ W0) {
    const int n = blockIdx.y;                 // 0..255
    const float* src = W0 + (size_t)n * NUMF;
    __half* dst = g_w0h + (size_t)n * NUMF;
    const int d4base = blockIdx.x * 1282;     // 8 * 1282 = 10256 = NUMF/4
    const int d4end  = d4base + 1282 < NUMF / 4 ? d4base + 1282 : NUMF / 4;
    for (int d4 = d4base + threadIdx.x; d4 < d4end; d4 += 256) {
        int d = d4 << 2;
        int r = d & 63, base = d & ~63;
        int slot = r >> 2;
        int t  = (slot & 1) | ((slot >> 3) << 1);
        int st = (slot >> 1) & 1;
        int c  = (slot >> 2) & 1;
        int K0 = base + c * 32 + 16 * (t >> 1) + 2 * (t & 1) + 8 * st;
        float2 v0 = *(const float2*)(src + K0);
        float2 v1 = *(const float2*)(src + K0 + 4);
        uint2 o;
        o.x = f2h2(v0.x, v0.y);
        o.y = f2h2(v1.x, v1.y);
        *(uint2*)(dst + d) = o;
    }
}

// ---------------- kernel 1: layer-0 GEMM (fp16 mma.sync, fp16 B, 148-CTA split) ----------------
__global__ void __launch_bounds__(288, 1) nn_gemm(
    const __grid_constant__ CUtensorMap tmW,
    const __grid_constant__ CUtensorMap tmB,
    const __grid_constant__ CUtensorMap tmW0h)
{
    extern __shared__ char raw[];
    char* base = (char*)(((uintptr_t)raw + 1023u) & ~(uintptr_t)1023u);
    uint32_t base_u   = smem_u32(base);
    uint32_t mb_full  = base_u;            // STAGES x 8B
    uint32_t mb_empty = base_u + 512;      // STAGES x 8B
    char* tiles       = base + 1024;
    uint32_t tiles_u  = base_u + 1024;

    const int tid  = threadIdx.x;
    const int wid  = tid >> 5;
    const int lane = tid & 31;
    const int bid  = blockIdx.x;

    const int cs = (int)((long long)bid * TOTC / GRID1);        // start chunk
    const int ce = (int)((long long)(bid + 1) * TOTC / GRID1);  // end chunk
    const int nc = ce - cs;                                     // 277 or 278
    const int mt0 = cs / CHPM;
    const int mt1 = (ce - 1) / CHPM;                            // mt0 or mt0+1

    if (tid == 0) {
        for (int s = 0; s < STAGES; s++) {
            mbar_init(mb_full  + s * 8, 1);
            mbar_init(mb_empty + s * 8, 256);
        }
        asm volatile("fence.proxy.async.shared::cta;" ::: "memory");
    }
    __syncthreads();

    if (wid == 8) {
        if (lane == 0) {
            // ---------------- producer ----------------
#define ISSUE(c_, s_) do {                                           \
            int mt_ = (c_) / CHPM;                                   \
            int kc_ = (c_) - mt_ * CHPM;                             \
            const CUtensorMap* mp_ = (mt_ < 32) ? &tmW : &tmB;       \
            uint32_t mb_ = mb_full + (s_) * 8;                       \
            mbar_expect_tx(mb_, STGB);                               \
            uint32_t t_ = tiles_u + (s_) * STGB;                     \
            tma2d(t_,         mp_,   kc_ * 64,      (mt_ & 31) * 128, mb_); \
            tma2d(t_ + 16384, mp_,   kc_ * 64 + 32, (mt_ & 31) * 128, mb_); \
            tma2d(t_ + ASTG, &tmW0h, kc_ * 64,      0,                mb_); \
        } while (0)
            ISSUE(cs, 0); ISSUE(cs + 1, 1); ISSUE(cs + 2, 2);
            int s = 0, ep = 0;
            for (int j = STAGES; j < nc; j++) {
                mbar_wait(mb_empty + s * 8, ep);
                ISSUE(cs + j, s);
                if (++s == STAGES) { s = 0; ep ^= 1; }
            }
#undef ISSUE
        }
    } else {
        // ---------------- consumers ----------------
        const int wm = (wid >> 2) * 64;      // warp M offset (0/64)
        const int wn = (wid & 3) * 64;       // warp N offset (0/64/128/192)
        const int g  = lane >> 2;            // 0..7
        const int t  = lane & 3;             // 0..3

        // A: conflict-free swizzled byte offsets (validated R7); st = kstep&1
        int aoff[2][2];
        #pragma unroll
        for (int s_ = 0; s_ < 2; s_++)
            #pragma unroll
            for (int h_ = 0; h_ < 2; h_++)
                aoff[s_][h_] = ((32 * s_ + 16 * h_ + 8 * (t & 1) + 64 * (t >> 1)) ^ (g << 4));
        // B: one LDS.64 per (ni, kstep); slot = P(t) + 2*st + 4*c
        const int Pt = (t & 1) + 8 * (t >> 1);
        int boff[4];
        #pragma unroll
        for (int ks = 0; ks < 4; ks++)
            boff[ks] = (((Pt + 2 * (ks & 1) + 4 * (ks >> 1)) * 8) ^ (g << 4));

        float c[4][8][4];
        #pragma unroll
        for (int mi = 0; mi < 4; mi++)
            #pragma unroll
            for (int ni = 0; ni < 8; ni++)
                #pragma unroll
                for (int r = 0; r < 4; r++) c[mi][ni][r] = 0.f;

        // local index of the last chunk of part 0 (or -1 if single part)
        const int jb = (mt1 > mt0) ? ((mt0 + 1) * CHPM - 1 - cs) : -1;

        int s = 0, fp = 0;
        for (int j = 0; j < nc; j++) {
            mbar_wait(mb_full + s * 8, fp);
            const char* Ast = tiles + s * STGB;
            const char* Bst = Ast + ASTG;

            #pragma unroll
            for (int ks = 0; ks < 4; ks++) {
                const char* Asub = Ast + (ks >> 1) * 16384;
                const int st = ks & 1;
                uint32_t a[4][4];
                #pragma unroll
                for (int mi = 0; mi < 4; mi++) {
                    const char* pr = Asub + (wm + mi * 16 + g) * 128;
                    float2 v00 = *(const float2*)(pr + aoff[st][0]);
                    float2 v10 = *(const float2*)(pr + 1024 + aoff[st][0]);
                    float2 v01 = *(const float2*)(pr + aoff[st][1]);
                    float2 v11 = *(const float2*)(pr + 1024 + aoff[st][1]);
                    a[mi][0] = f2h2(v00.x, v00.y);
                    a[mi][1] = f2h2(v10.x, v10.y);
                    a[mi][2] = f2h2(v01.x, v01.y);
                    a[mi][3] = f2h2(v11.x, v11.y);
                }
                uint32_t b[8][2];
                #pragma unroll
                for (int ni = 0; ni < 8; ni++) {
                    uint2 v = *(const uint2*)(Bst + (wn + ni * 8 + g) * 128 + boff[ks]);
                    b[ni][0] = v.x; b[ni][1] = v.y;
                }
                #pragma unroll
                for (int mi = 0; mi < 4; mi++)
                    #pragma unroll
                    for (int ni = 0; ni < 8; ni++)
                        mma_f16(c[mi][ni], a[mi], b[ni]);
            }
            mbar_arrive(mb_empty + s * 8);
            if (++s == STAGES) { s = 0; fp ^= 1; }

            if (j == jb) {
                // flush part 0, reset accumulators
                float* dst = g_part[bid][0];
                #pragma unroll
                for (int ni = 0; ni < 8; ni++) {
                    const int col = wn + ni * 8 + (t << 1);
                    #pragma unroll
                    for (int mi = 0; mi < 4; mi++) {
                        const int r = wm + mi * 16 + g;
                        *(float2*)(dst + (size_t)r * 256 + col)       = make_float2(c[mi][ni][0], c[mi][ni][1]);
                        *(float2*)(dst + (size_t)(r + 8) * 256 + col) = make_float2(c[mi][ni][2], c[mi][ni][3]);
                        c[mi][ni][0] = c[mi][ni][1] = c[mi][ni][2] = c[mi][ni][3] = 0.f;
                    }
                }
            }
        }

        // final flush (part 1 if two parts, else part 0)
        {
            float* dst = g_part[bid][(mt1 > mt0) ? 1 : 0];
            #pragma unroll
            for (int ni = 0; ni < 8; ni++) {
                const int col = wn + ni * 8 + (t << 1);
                #pragma unroll
                for (int mi = 0; mi < 4; mi++) {
                    const int r = wm + mi * 16 + g;
                    *(float2*)(dst + (size_t)r * 256 + col)       = make_float2(c[mi][ni][0], c[mi][ni][1]);
                    *(float2*)(dst + (size_t)(r + 8) * 256 + col) = make_float2(c[mi][ni][2], c[mi][ni][3]);
                }
            }
        }
    }
}

// ---------------- kernel 1.5: reduce partials -> dense g_acc (+b0) ----------------
__device__ __forceinline__ int cover_cta(int c) {
    return (int)(((long long)(c + 1) * GRID1 - 1) / TOTC);
}
__device__ __forceinline__ int gather_parts(int mt, const float** ptr) {
    int c0 = mt * CHPM;
    int iA = cover_cta(c0);
    int iB = cover_cta(c0 + CHPM - 1);
    int n = 0;
    for (int i = iA; i <= iB && n < 4; i++) {
        int si = (int)((long long)i * TOTC / GRID1);
        int slot = (si / CHPM == mt) ? 0 : 1;
        ptr[n++] = g_part[i][slot];
    }
    return n;
}

__global__ void __launch_bounds__(256) nn_reduce(const float* __restrict__ b0) {
    const int mt   = blockIdx.x >> 3;       // M-tile 0..63
    const int slab = blockIdx.x & 7;        // rows [slab*16, slab*16+16)
    const float* ps[4];
    const int n = gather_parts(mt, ps);

    const int base = slab * 16 * 256;       // float offset within tile
    float* dst = g_acc + (size_t)mt * 128 * 256 + base;
    const float4* b0v = (const float4*)b0;

    for (int i = threadIdx.x; i < 1024; i += 256) {
        float4 s = b0v[i & 63];
        #pragma unroll 4
        for (int k = 0; k < 4; k++) {
            if (k < n) {
                float4 v = ((const float4*)(ps[k] + base))[i];
                s.x += v.x; s.y += v.y; s.z += v.z; s.w += v.w;
            }
        }
        ((float4*)dst)[i] = s;
    }
}

// ---------------- kernel 2: blend + clip + small MLP head (vectorized, 4-acc) ----------------
#define SW1_PITCH 516
#define SW2_PITCH 36
#define SMEM2 ((32*SW1_PITCH + 32*SW2_PITCH + 16*512 + 16*32) * 4)

__device__ __forceinline__ float4 clip4(float4 v) {
    v.x = fminf(fmaxf(v.x, 0.f), 1.f);
    v.y = fminf(fmaxf(v.y, 0.f), 1.f);
    v.z = fminf(fmaxf(v.z, 0.f), 1.f);
    v.w = fminf(fmaxf(v.w, 0.f), 1.f);
    return v;
}

__global__ void __launch_bounds__(512) nn_head(
    const float* __restrict__ stm,
    const float* __restrict__ W1, const float* __restrict__ b1,
    const float* __restrict__ W2, const float* __restrict__ b2,
    const float* __restrict__ W3, const float* __restrict__ b3,
    float* __restrict__ out)
{
    extern __shared__ float sm[];
    float* sW1 = sm;                               // 32 x 516
    float* sW2 = sW1 + 32 * SW1_PITCH;             // 32 x 36
    float* sl1 = sW2 + 32 * SW2_PITCH;             // 16 warps x 512
    float* sl2 = sl1 + 16 * 512;                   // 16 warps x 32

    int tid = threadIdx.x;
    int w = tid >> 5, j = tid & 31;
    int b = blockIdx.x * 16 + w;

    const float4* aw = (const float4*)(g_acc + (size_t)b * 256);
    const float4* ab = (const float4*)(g_acc + (size_t)(4096 + b) * 256);
    float4 wv0 = aw[j],      bv0 = ab[j];
    float4 wv1 = aw[32 + j], bv1 = ab[32 + j];
    float s = stm[b];

    for (int i = tid; i < 32 * 512; i += 512) sW1[(i >> 9) * SW1_PITCH + (i & 511)] = W1[i];
    for (int i = tid; i < 32 * 32;  i += 512) sW2[(i >> 5) * SW2_PITCH + (i & 31)]  = W2[i];
    __syncthreads();

    float4* l14 = (float4*)(sl1 + w * 512);
    float*  l2  = sl2 + w * 32;
    float bj1 = b1[j], bj2 = b2[j], w3j = W3[j], b3v = b3[0];
    const float t1 = 1.f - s;

    {
        float4 x0, x1, y0, y1;
        x0.x = s*wv0.x + t1*bv0.x; x0.y = s*wv0.y + t1*bv0.y; x0.z = s*wv0.z + t1*bv0.z; x0.w = s*wv0.w + t1*bv0.w;
        y0.x = s*bv0.x + t1*wv0.x; y0.y = s*bv0.y + t1*wv0.y; y0.z = s*bv0.z + t1*wv0.z; y0.w = s*bv0.w + t1*wv0.w;
        x1.x = s*wv1.x + t1*bv1.x; x1.y = s*wv1.y + t1*bv1.y; x1.z = s*wv1.z + t1*bv1.z; x1.w = s*wv1.w + t1*bv1.w;
        y1.x = s*bv1.x + t1*wv1.x; y1.y = s*bv1.y + t1*wv1.y; y1.z = s*bv1.z + t1*wv1.z; y1.w = s*bv1.w + t1*wv1.w;
        l14[j]       = clip4(x0);
        l14[32 + j]  = clip4(x1);
        l14[64 + j]  = clip4(y0);
        l14[96 + j]  = clip4(y1);
    }
    __syncwarp();

    float a0 = bj1, a1 = 0.f, a2c = 0.f, a3c = 0.f;
    const float4* wr = (const float4*)(sW1 + j * SW1_PITCH);
    #pragma unroll 16
    for (int k = 0; k < 128; k++) {
        float4 v = wr[k], u = l14[k];
        a0  += v.x * u.x;
        a1  += v.y * u.y;
        a2c += v.z * u.z;
        a3c += v.w * u.w;
    }
    float a2 = fminf(fmaxf((a0 + a1) + (a2c + a3c), 0.f), 1.f);
    l2[j] = a2;
    __syncwarp();

    float c0 = bj2, c1 = 0.f, c2 = 0.f, c3 = 0.f;
    const float4* wr2 = (const float4*)(sW2 + j * SW2_PITCH);
    const float4* l24 = (const float4*)l2;
    #pragma unroll
    for (int k = 0; k < 8; k++) {
        float4 v = wr2[k], u = l24[k];
        c0 += v.x * u.x; c1 += v.y * u.y; c2 += v.z * u.z; c3 += v.w * u.w;
    }
    float a3 = fminf(fmaxf((c0 + c1) + (c2 + c3), 0.f), 1.f);
    float v = w3j * a3;
    #pragma unroll
    for (int o = 16; o > 0; o >>= 1) v += __shfl_xor_sync(0xffffffffu, v, o);
    if (j == 0) out[b] = v + b3v;
}

// ---------------- host ----------------
typedef CUresult (*EncodeFn)(CUtensorMap*, CUtensorMapDataType, cuuint32_t, void*,
                             const cuuint64_t*, const cuuint64_t*, const cuuint32_t*, const cuuint32_t*,
                             CUtensorMapInterleave, CUtensorMapSwizzle,
                             CUtensorMapL2promotion, CUtensorMapFloatOOBfill);

static EncodeFn get_encoder() {
    void* p = nullptr;
    cudaDriverEntryPointQueryResult qr;
    cudaGetDriverEntryPointByVersion("cuTensorMapEncodeTiled", &p, 12000, cudaEnableDefault, &qr);
    return (EncodeFn)p;
}

static void encode_f32(CUtensorMap* m, const void* ptr, unsigned long long rows) {
    cuuint64_t dims[2]    = { (cuuint64_t)NUMF, (cuuint64_t)rows };
    cuuint64_t strides[1] = { (cuuint64_t)NUMF * 4ull };
    cuuint32_t box[2]     = { 32u, 128u };      // 128B x 128 rows, SW128
    cuuint32_t es[2]      = { 1u, 1u };
    get_encoder()(m, CU_TENSOR_MAP_DATA_TYPE_FLOAT32, 2, (void*)ptr, dims, strides, box, es,
       CU_TENSOR_MAP_INTERLEAVE_NONE, CU_TENSOR_MAP_SWIZZLE_128B,
       CU_TENSOR_MAP_L2_PROMOTION_L2_128B, CU_TENSOR_MAP_FLOAT_OOB_FILL_NONE);
}

static void encode_f16(CUtensorMap* m, const void* ptr, unsigned long long rows) {
    cuuint64_t dims[2]    = { (cuuint64_t)NUMF, (cuuint64_t)rows };
    cuuint64_t strides[1] = { (cuuint64_t)NUMF * 2ull };
    cuuint32_t box[2]     = { 64u, 256u };      // 128B x 256 rows, SW128
    cuuint32_t es[2]      = { 1u, 1u };
    get_encoder()(m, CU_TENSOR_MAP_DATA_TYPE_FLOAT16, 2, (void*)ptr, dims, strides, box, es,
       CU_TENSOR_MAP_INTERLEAVE_NONE, CU_TENSOR_MAP_SWIZZLE_128B,
       CU_TENSOR_MAP_L2_PROMOTION_L2_128B, CU_TENSOR_MAP_FLOAT_OOB_FILL_NONE);
}

extern "C" void kernel_launch(void* const* d_in, const int* in_sizes, int n_in,
                              void* d_out, int out_size) {
    const float* wf  = (const float*)d_in[0];
    const float* bf  = (const float*)d_in[1];
    const float* stm = (const float*)d_in[2];
    const float* W0  = (const float*)d_in[3];
    const float* b0  = (const float*)d_in[4];
    const float* W1  = (const float*)d_in[5];
    const float* b1  = (const float*)d_in[6];
    const float* W2  = (const float*)d_in[7];
    const float* b2  = (const float*)d_in[8];
    const float* W3  = (const float*)d_in[9];
    const float* b3  = (const float*)d_in[10];
    float* out = (float*)d_out;

    void* w0h_ptr = nullptr;
    cudaGetSymbolAddress(&w0h_ptr, g_w0h);

    CUtensorMap mW, mB, mW0h;
    encode_f32(&mW,  wf, 4096);
    encode_f32(&mB,  bf, 4096);
    encode_f16(&mW0h, w0h_ptr, 256);

    cudaFuncSetAttribute(nn_gemm, cudaFuncAttributeMaxDynamicSharedMemorySize, SMEM1);
    cudaFuncSetAttribute(nn_head, cudaFuncAttributeMaxDynamicSharedMemorySize, SMEM2);

    nn_cvt<<<dim3(8, 256), 256>>>(W0);
    nn_gemm<<<GRID1, 288, SMEM1>>>(mW, mB, mW0h);
    nn_reduce<<<512, 256>>>(b0);
    nn_head<<<256, 512, SMEM2>>>(stm, W1, b1, W2, b2, W3, b3, out);
}